// round 7
// baseline (speedup 1.0000x reference)
#include <cuda_runtime.h>
#include <cuda_bf16.h>
#include <cstdint>

#define B_SZ   1024
#define K_SZ   512
#define D_SZ   256
#define H_SZ   8
#define HD_SZ  32
#define EPS_LN 1e-5f
#define Q_SCALE 0.17677669529663687f   // 32^-0.5

// ---------------- scratch (device globals; allocation-free) ----------------
__device__ float g_q[B_SZ * D_SZ];                        // 1 MB
__device__ float g_k[(size_t)B_SZ * K_SZ * D_SZ];         // 512 MB
__device__ float g_v[(size_t)B_SZ * K_SZ * D_SZ];         // 512 MB
__device__ __nv_bfloat16 g_wh[2][D_SZ * D_SZ];            // W hi (0=Wk,1=Wv)
__device__ __nv_bfloat16 g_wl[2][D_SZ * D_SZ];            // W lo

// ======================= helpers ==============================
__device__ __forceinline__ uint32_t smem_u32(const void* p) {
    uint32_t a;
    asm("{ .reg .u64 t; cvta.to.shared.u64 t, %1; cvt.u32.u64 %0, t; }"
        : "=r"(a) : "l"(p));
    return a;
}
__device__ __forceinline__ uint32_t pack_bf2(float a, float b) {
    __nv_bfloat162 t = __floats2bfloat162_rn(a, b);
    return *reinterpret_cast<uint32_t*>(&t);
}

#define LDSM4(r0, r1, r2, r3, addr) \
    asm volatile("ldmatrix.sync.aligned.m8n8.x4.shared.b16 {%0,%1,%2,%3}, [%4];" \
                 : "=r"(r0), "=r"(r1), "=r"(r2), "=r"(r3) : "r"(addr))

#define MMA16816(c, a, b) \
    asm volatile("mma.sync.aligned.m16n8k16.row.col.f32.bf16.bf16.f32 " \
                 "{%0,%1,%2,%3}, {%4,%5,%6,%7}, {%8,%9}, {%0,%1,%2,%3};" \
                 : "+f"((c)[0]), "+f"((c)[1]), "+f"((c)[2]), "+f"((c)[3]) \
                 : "r"((a)[0]), "r"((a)[1]), "r"((a)[2]), "r"((a)[3]), \
                   "r"((b)[0]), "r"((b)[1]))

#define CP16(dst, gsrc) \
    asm volatile("cp.async.ca.shared.global [%0], [%1], 16;" \
                 :: "r"(dst), "l"(gsrc) : "memory")
#define CP_COMMIT() asm volatile("cp.async.commit_group;" ::: "memory")
#define CP_WAIT0()  asm volatile("cp.async.wait_group 0;" ::: "memory")

// ============================================================================
// Kernel 0: split Wk/Wv into bf16 hi/lo.  grid=512, block=256
// ============================================================================
__global__ void wsplit_kernel(const float* __restrict__ Wk,
                              const float* __restrict__ Wv)
{
    const int sel = blockIdx.x & 1;
    const int i   = (blockIdx.x >> 1) * 256 + threadIdx.x;
    const float w = (sel ? Wv : Wk)[i];
    const __nv_bfloat16 hi = __float2bfloat16(w);
    g_wh[sel][i] = hi;
    g_wl[sel][i] = __float2bfloat16(w - __bfloat162float(hi));
}

// ============================================================================
// Kernel 1: q = LN_perhead(x_q @ Wq^T) * scale          grid=B, block=256
// ============================================================================
__global__ void qproj_kernel(const float* __restrict__ xq,
                             const float* __restrict__ Wq,
                             const float* __restrict__ qn_w,
                             const float* __restrict__ qn_b)
{
    const int b = blockIdx.x;
    const int j = threadIdx.x;
    const int lane = j & 31;

    __shared__ float xrow[D_SZ];
    xrow[j] = xq[b * D_SZ + j];
    __syncthreads();

    const float4* w4 = reinterpret_cast<const float4*>(Wq + (size_t)j * D_SZ);
    const float4* x4 = reinterpret_cast<const float4*>(xrow);
    float acc = 0.f;
#pragma unroll
    for (int d = 0; d < D_SZ / 4; ++d) {
        float4 w = w4[d];
        float4 x = x4[d];
        acc = fmaf(w.x, x.x, acc);
        acc = fmaf(w.y, x.y, acc);
        acc = fmaf(w.z, x.z, acc);
        acc = fmaf(w.w, x.w, acc);
    }
    float s = acc, ss = acc * acc;
#pragma unroll
    for (int o = 16; o > 0; o >>= 1) {
        s  += __shfl_xor_sync(0xffffffffu, s,  o);
        ss += __shfl_xor_sync(0xffffffffu, ss, o);
    }
    const float mu  = s * (1.f / 32.f);
    const float var = ss * (1.f / 32.f) - mu * mu;
    const float r   = rsqrtf(var + EPS_LN);
    float q = (acc - mu) * r * qn_w[lane] + qn_b[lane];
    g_q[b * D_SZ + j] = q * Q_SCALE;
}

// ============================================================================
// Kernel 2 (mma.sync bf16 hi/lo): Out[M,256] = X[M,256] @ W^T
//   CTA: M=64, N=256, K chunks of 64, double-buffered smem, SW128 swizzle.
//   512 threads / 16 warps; warp (mh=w>>3, h=w&7) owns rows [32mh,+32) x
//   cols [32h,+32) (head h). 3 MMA passes: hiA*hiW + loA*hiW + hiA*loW.
// ============================================================================
#define CH       64
#define NCH      (D_SZ / CH)      // 4
#define OFF_AH   0                 // 64 rows * 128B = 8 KB
#define OFF_AL   8192
#define OFF_WH   16384             // 256 rows * 128B = 32 KB
#define OFF_WL   49152
#define STAGE_B  81920             // 80 KB per stage
#define DSM_B    (2 * STAGE_B + 1024)
#define PT       512

template<bool DO_LN>
__global__ void __launch_bounds__(PT, 1)
proj_mma(const float* __restrict__ X, int wsel,
         const float* __restrict__ lnw, const float* __restrict__ lnb)
{
    extern __shared__ char dsm[];
    char* smp = (char*)((((uintptr_t)dsm) + 1023) & ~(uintptr_t)1023);
    const uint32_t base = smem_u32(smp);

    const int tid  = threadIdx.x;
    const int wid  = tid >> 5;
    const int lane = tid & 31;
    const int mh   = wid >> 3;       // 0/1 : which 32-row half
    const int h    = wid & 7;        // head / 32-col stripe
    const size_t m_base = (size_t)blockIdx.x * 64;

    const __nv_bfloat16* __restrict__ Wh = g_wh[wsel];
    const __nv_bfloat16* __restrict__ Wl = g_wl[wsel];

    // LN gamma/beta per thread-column
    float lw[4][2], lb[4][2];
    if (DO_LN) {
#pragma unroll
        for (int j = 0; j < 4; ++j) {
            const int c = 8 * j + 2 * (lane & 3);
            lw[j][0] = lnw[c];     lw[j][1] = lnw[c + 1];
            lb[j][0] = lnb[c];     lb[j][1] = lnb[c + 1];
        }
    }

    // ---- X load/convert mapping: thread -> row tid>>3, 8 floats ----
    const int xrow = tid >> 3;             // 0..63
    const int xc8  = tid & 7;              // which 8-float group in 64-chunk
    const float* xptr = X + (m_base + xrow) * D_SZ + xc8 * 8;
    const uint32_t xoff = (uint32_t)xrow * 128u +
                          (((uint32_t)xc8 * 16u) ^ ((uint32_t)(xrow & 7) * 16u));

    float acc[2][4][4];
#pragma unroll
    for (int i = 0; i < 2; ++i)
#pragma unroll
        for (int j = 0; j < 4; ++j)
#pragma unroll
            for (int cc = 0; cc < 4; ++cc) acc[i][j][cc] = 0.f;

    float4 xr[2];

    // ================= prologue: stage 0 = chunk 0 =================
    {
        const uint32_t wb = base;
#pragma unroll
        for (int i = 0; i < 4; ++i) {
            const int idx = tid + i * PT;
            const int row = idx >> 3;
            const int j16 = idx & 7;
            const uint32_t off = (uint32_t)row * 128u +
                                 (((uint32_t)j16 * 16u) ^ ((uint32_t)(row & 7) * 16u));
            CP16(wb + OFF_WH + off, (const char*)Wh + (size_t)row * 512 + j16 * 16);
            CP16(wb + OFF_WL + off, (const char*)Wl + (size_t)row * 512 + j16 * 16);
        }
        CP_COMMIT();
        xr[0] = *reinterpret_cast<const float4*>(xptr);
        xr[1] = *reinterpret_cast<const float4*>(xptr + 4);
        {
            uint4 hv, lv;
            hv.x = pack_bf2(xr[0].x, xr[0].y);
            hv.y = pack_bf2(xr[0].z, xr[0].w);
            hv.z = pack_bf2(xr[1].x, xr[1].y);
            hv.w = pack_bf2(xr[1].z, xr[1].w);
            lv.x = pack_bf2(xr[0].x - __bfloat162float(__float2bfloat16(xr[0].x)),
                            xr[0].y - __bfloat162float(__float2bfloat16(xr[0].y)));
            lv.y = pack_bf2(xr[0].z - __bfloat162float(__float2bfloat16(xr[0].z)),
                            xr[0].w - __bfloat162float(__float2bfloat16(xr[0].w)));
            lv.z = pack_bf2(xr[1].x - __bfloat162float(__float2bfloat16(xr[1].x)),
                            xr[1].y - __bfloat162float(__float2bfloat16(xr[1].y)));
            lv.w = pack_bf2(xr[1].z - __bfloat162float(__float2bfloat16(xr[1].z)),
                            xr[1].w - __bfloat162float(__float2bfloat16(xr[1].w)));
            *reinterpret_cast<uint4*>(smp + OFF_AH + xoff) = hv;
            *reinterpret_cast<uint4*>(smp + OFF_AL + xoff) = lv;
        }
        CP_WAIT0();
        __syncthreads();
    }

    // ================= main loop over K chunks =================
    for (int c = 0; c < NCH; ++c) {
        const int s = c & 1;
        const uint32_t sb = base + s * STAGE_B;

        if (c + 1 < NCH) {
            const int kn = (c + 1) * CH;
            const uint32_t wb = base + (s ^ 1) * STAGE_B;
#pragma unroll
            for (int i = 0; i < 4; ++i) {
                const int idx = tid + i * PT;
                const int row = idx >> 3;
                const int j16 = idx & 7;
                const uint32_t off = (uint32_t)row * 128u +
                                     (((uint32_t)j16 * 16u) ^ ((uint32_t)(row & 7) * 16u));
                CP16(wb + OFF_WH + off,
                     (const char*)Wh + (size_t)row * 512 + kn * 2 + j16 * 16);
                CP16(wb + OFF_WL + off,
                     (const char*)Wl + (size_t)row * 512 + kn * 2 + j16 * 16);
            }
            CP_COMMIT();
            xr[0] = *reinterpret_cast<const float4*>(xptr + kn);
            xr[1] = *reinterpret_cast<const float4*>(xptr + kn + 4);
        }

        // ---------------- compute chunk c ----------------
#pragma unroll
        for (int ks = 0; ks < 4; ++ks) {
            uint32_t Ah4[2][4], Al4[2][4], Bh4[4][2], Bl4[4][2];
            {
                const int ar = lane & 15;
                const uint32_t akhb = (uint32_t)(lane >> 4) * 16u;
#pragma unroll
                for (int i = 0; i < 2; ++i) {
                    const int row = 32 * mh + 16 * i + ar;
                    const uint32_t off = (uint32_t)row * 128u +
                        (((uint32_t)ks * 32u + akhb) ^ ((uint32_t)(row & 7) * 16u));
                    LDSM4(Ah4[i][0], Ah4[i][1], Ah4[i][2], Ah4[i][3], sb + OFF_AH + off);
                    LDSM4(Al4[i][0], Al4[i][1], Al4[i][2], Al4[i][3], sb + OFF_AL + off);
                }
            }
            {
                const int g2  = lane >> 3;
                const uint32_t khb = (uint32_t)(g2 & 1) * 16u;
                const int rsub = ((g2 >> 1) * 8) + (lane & 7);
#pragma unroll
                for (int p = 0; p < 2; ++p) {
                    const int row = h * 32 + p * 16 + rsub;
                    const uint32_t off = (uint32_t)row * 128u +
                        (((uint32_t)ks * 32u + khb) ^ ((uint32_t)(row & 7) * 16u));
                    LDSM4(Bh4[2 * p][0], Bh4[2 * p][1], Bh4[2 * p + 1][0], Bh4[2 * p + 1][1],
                          sb + OFF_WH + off);
                    LDSM4(Bl4[2 * p][0], Bl4[2 * p][1], Bl4[2 * p + 1][0], Bl4[2 * p + 1][1],
                          sb + OFF_WL + off);
                }
            }
#pragma unroll
            for (int i = 0; i < 2; ++i)
#pragma unroll
                for (int j = 0; j < 4; ++j) {
                    MMA16816(acc[i][j], Ah4[i], Bh4[j]);
                    MMA16816(acc[i][j], Al4[i], Bh4[j]);
                    MMA16816(acc[i][j], Ah4[i], Bl4[j]);
                }
        }

        // ---------------- stage X for chunk c+1 ----------------
        if (c + 1 < NCH) {
            char* ab = smp + (s ^ 1) * STAGE_B;
            uint4 hv, lv;
            hv.x = pack_bf2(xr[0].x, xr[0].y);
            hv.y = pack_bf2(xr[0].z, xr[0].w);
            hv.z = pack_bf2(xr[1].x, xr[1].y);
            hv.w = pack_bf2(xr[1].z, xr[1].w);
            lv.x = pack_bf2(xr[0].x - __bfloat162float(__float2bfloat16(xr[0].x)),
                            xr[0].y - __bfloat162float(__float2bfloat16(xr[0].y)));
            lv.y = pack_bf2(xr[0].z - __bfloat162float(__float2bfloat16(xr[0].z)),
                            xr[0].w - __bfloat162float(__float2bfloat16(xr[0].w)));
            lv.z = pack_bf2(xr[1].x - __bfloat162float(__float2bfloat16(xr[1].x)),
                            xr[1].y - __bfloat162float(__float2bfloat16(xr[1].y)));
            lv.w = pack_bf2(xr[1].z - __bfloat162float(__float2bfloat16(xr[1].z)),
                            xr[1].w - __bfloat162float(__float2bfloat16(xr[1].w)));
            *reinterpret_cast<uint4*>(ab + OFF_AH + xoff) = hv;
            *reinterpret_cast<uint4*>(ab + OFF_AL + xoff) = lv;
            CP_WAIT0();
        }
        __syncthreads();
    }

    // ================= epilogue: per-head LN + store =================
    float* __restrict__ Out = DO_LN ? g_k : g_v;
    const int g  = lane >> 2;
    const int tg = lane & 3;
    const int ncol = h * 32 + 2 * tg;

#pragma unroll
    for (int i = 0; i < 2; ++i) {
#pragma unroll
        for (int half = 0; half < 2; ++half) {
            const int r = 32 * mh + 16 * i + 8 * half + g;
            float v0[4], v1[4];
#pragma unroll
            for (int j = 0; j < 4; ++j) {
                v0[j] = acc[i][j][2 * half];
                v1[j] = acc[i][j][2 * half + 1];
            }
            if (DO_LN) {
                float s = 0.f, ss = 0.f;
#pragma unroll
                for (int j = 0; j < 4; ++j) {
                    s  += v0[j] + v1[j];
                    ss += v0[j] * v0[j] + v1[j] * v1[j];
                }
                s  += __shfl_xor_sync(0xffffffffu, s,  1);
                ss += __shfl_xor_sync(0xffffffffu, ss, 1);
                s  += __shfl_xor_sync(0xffffffffu, s,  2);
                ss += __shfl_xor_sync(0xffffffffu, ss, 2);
                const float mu  = s * (1.f / 32.f);
                const float var = ss * (1.f / 32.f) - mu * mu;
                const float rr  = rsqrtf(var + EPS_LN);
#pragma unroll
                for (int j = 0; j < 4; ++j) {
                    v0[j] = (v0[j] - mu) * rr * lw[j][0] + lb[j][0];
                    v1[j] = (v1[j] - mu) * rr * lw[j][1] + lb[j][1];
                }
            }
            float* orow = Out + (m_base + r) * D_SZ + ncol;
#pragma unroll
            for (int j = 0; j < 4; ++j)
                *reinterpret_cast<float2*>(orow + 8 * j) = make_float2(v0[j], v1[j]);
        }
    }
}

// ============================================================================
// Kernel 3: single-query attention, thread-per-k-row + output LN + Wp.
//   grid=B, block=256; warp = head; thread owns whole 128B k/v row slices.
// ============================================================================
__global__ void __launch_bounds__(256, 4)
attn_kernel(const float* __restrict__ Wp,
            const float* __restrict__ n_w,
            const float* __restrict__ n_b,
            float* __restrict__ out)
{
    const int b    = blockIdx.x;
    const int tid  = threadIdx.x;
    const int h    = tid >> 5;
    const int lane = tid & 31;

    __shared__ float sq[D_SZ];
    sq[tid] = g_q[b * D_SZ + tid];
    __syncthreads();

    float q[32];
    {
        const float4* qh = reinterpret_cast<const float4*>(sq + h * HD_SZ);
#pragma unroll
        for (int i = 0; i < 8; ++i) {
            float4 v = qh[i];
            q[4 * i] = v.x; q[4 * i + 1] = v.y; q[4 * i + 2] = v.z; q[4 * i + 3] = v.w;
        }
    }

    const float* kbase = g_k + (size_t)b * K_SZ * D_SZ + h * HD_SZ;
    const float* vbase = g_v + (size_t)b * K_SZ * D_SZ + h * HD_SZ;

    float m = -1e30f, l = 0.f;
    float acc[32];
#pragma unroll
    for (int d = 0; d < 32; ++d) acc[d] = 0.f;

#pragma unroll 2
    for (int it = 0; it < 16; ++it) {
        const int r = lane + it * 32;
        const float4* kp = reinterpret_cast<const float4*>(kbase + (size_t)r * D_SZ);
        const float4* vp = reinterpret_cast<const float4*>(vbase + (size_t)r * D_SZ);
        float4 kr[8], vr[8];
#pragma unroll
        for (int i = 0; i < 8; ++i) kr[i] = kp[i];
#pragma unroll
        for (int i = 0; i < 8; ++i) vr[i] = vp[i];

        float s = 0.f;
#pragma unroll
        for (int i = 0; i < 8; ++i) {
            s = fmaf(kr[i].x, q[4 * i],     s);
            s = fmaf(kr[i].y, q[4 * i + 1], s);
            s = fmaf(kr[i].z, q[4 * i + 2], s);
            s = fmaf(kr[i].w, q[4 * i + 3], s);
        }
        const float mn   = fmaxf(m, s);
        const float corr = __expf(m - mn);
        const float p    = __expf(s - mn);
        l = l * corr + p;
#pragma unroll
        for (int i = 0; i < 8; ++i) {
            acc[4 * i]     = fmaf(corr, acc[4 * i],     p * vr[i].x);
            acc[4 * i + 1] = fmaf(corr, acc[4 * i + 1], p * vr[i].y);
            acc[4 * i + 2] = fmaf(corr, acc[4 * i + 2], p * vr[i].z);
            acc[4 * i + 3] = fmaf(corr, acc[4 * i + 3], p * vr[i].w);
        }
        m = mn;
    }

    // ---- merge 32 per-thread flash states across the warp ----
    float M = m;
#pragma unroll
    for (int o = 16; o > 0; o >>= 1)
        M = fmaxf(M, __shfl_xor_sync(0xffffffffu, M, o));
    const float c = __expf(m - M);
    l *= c;
#pragma unroll
    for (int d = 0; d < 32; ++d) acc[d] *= c;
#pragma unroll
    for (int o = 16; o > 0; o >>= 1)
        l += __shfl_xor_sync(0xffffffffu, l, o);

    // transpose-reduce: after this, lane d holds sum_k p_k v_k[d]
#pragma unroll
    for (int o = 16; o > 0; o >>= 1) {
#pragma unroll
        for (int d = 0; d < 16; ++d) {
            if (d < o) {
                const bool hi = (lane & o) != 0;
                const float keep = hi ? acc[d + o] : acc[d];
                const float send = hi ? acc[d]     : acc[d + o];
                acc[d] = keep + __shfl_xor_sync(0xffffffffu, send, o);
            }
        }
    }
    const float o_val = acc[0] / l;

    // ---- block LN over 256 channels ----
    __shared__ float sred[2][8];
    float s = o_val, ss = o_val * o_val;
#pragma unroll
    for (int o = 16; o > 0; o >>= 1) {
        s  += __shfl_xor_sync(0xffffffffu, s,  o);
        ss += __shfl_xor_sync(0xffffffffu, ss, o);
    }
    if (lane == 0) { sred[0][h] = s; sred[1][h] = ss; }
    __syncthreads();
    float ts = 0.f, tss = 0.f;
#pragma unroll
    for (int i = 0; i < 8; ++i) { ts += sred[0][i]; tss += sred[1][i]; }
    const float mu  = ts * (1.f / 256.f);
    const float var = tss * (1.f / 256.f) - mu * mu;
    const float r   = rsqrtf(var + EPS_LN);

    __shared__ float sn[D_SZ];
    sn[tid] = (o_val - mu) * r * n_w[tid] + n_b[tid];
    __syncthreads();

    const float4* w4 = reinterpret_cast<const float4*>(Wp + (size_t)tid * D_SZ);
    const float4* x4 = reinterpret_cast<const float4*>(sn);
    float a = 0.f;
#pragma unroll
    for (int d = 0; d < D_SZ / 4; ++d) {
        float4 w = w4[d];
        float4 x = x4[d];
        a = fmaf(w.x, x.x, a);
        a = fmaf(w.y, x.y, a);
        a = fmaf(w.z, x.z, a);
        a = fmaf(w.w, x.w, a);
    }
    out[b * D_SZ + tid] = a;
}

// ============================================================================
extern "C" void kernel_launch(void* const* d_in, const int* in_sizes, int n_in,
                              void* d_out, int out_size)
{
    const float* x_q  = (const float*)d_in[0];
    const float* x_k  = (const float*)d_in[1];
    const float* x_v  = (const float*)d_in[2];
    const float* Wq   = (const float*)d_in[3];
    const float* Wk   = (const float*)d_in[4];
    const float* Wv   = (const float*)d_in[5];
    const float* Wp   = (const float*)d_in[6];
    const float* qn_w = (const float*)d_in[7];
    const float* qn_b = (const float*)d_in[8];
    const float* kn_w = (const float*)d_in[9];
    const float* kn_b = (const float*)d_in[10];
    const float* n_w  = (const float*)d_in[11];
    const float* n_b  = (const float*)d_in[12];
    float* out = (float*)d_out;

    static int smem_set = 0;
    if (!smem_set) {
        cudaFuncSetAttribute(proj_mma<true>,
                             cudaFuncAttributeMaxDynamicSharedMemorySize, DSM_B);
        cudaFuncSetAttribute(proj_mma<false>,
                             cudaFuncAttributeMaxDynamicSharedMemorySize, DSM_B);
        smem_set = 1;
    }

    const int M_TILES = (B_SZ * K_SZ) / 64;   // 8192

    wsplit_kernel<<<512, 256>>>(Wk, Wv);
    qproj_kernel<<<B_SZ, 256>>>(x_q, Wq, qn_w, qn_b);
    proj_mma<true ><<<M_TILES, PT, DSM_B>>>(x_k, 0, kn_w, kn_b);
    proj_mma<false><<<M_TILES, PT, DSM_B>>>(x_v, 1, nullptr, nullptr);
    attn_kernel<<<B_SZ, 256>>>(Wp, n_w, n_b, out);
}

// round 8
// speedup vs baseline: 1.4021x; 1.4021x over previous
#include <cuda_runtime.h>
#include <cuda_bf16.h>
#include <cuda_fp16.h>
#include <cstdint>

#define B_SZ   1024
#define K_SZ   512
#define D_SZ   256
#define H_SZ   8
#define HD_SZ  32
#define EPS_LN 1e-5f
#define Q_SCALE 0.17677669529663687f   // 32^-0.5

// ---------------- scratch (device globals; allocation-free) ----------------
__device__ float g_q[B_SZ * D_SZ];                        // 1 MB
__device__ float g_k[(size_t)B_SZ * K_SZ * D_SZ];         // 512 MB
__device__ float g_v[(size_t)B_SZ * K_SZ * D_SZ];         // 512 MB
__device__ __half g_wh[2][D_SZ * D_SZ];                   // W fp16 (0=Wk,1=Wv)

// ======================= helpers ==============================
__device__ __forceinline__ uint32_t smem_u32(const void* p) {
    uint32_t a;
    asm("{ .reg .u64 t; cvta.to.shared.u64 t, %1; cvt.u32.u64 %0, t; }"
        : "=r"(a) : "l"(p));
    return a;
}
__device__ __forceinline__ uint32_t pack_h2(float a, float b) {
    __half2 t = __floats2half2_rn(a, b);
    return *reinterpret_cast<uint32_t*>(&t);
}

#define LDSM4(r0, r1, r2, r3, addr) \
    asm volatile("ldmatrix.sync.aligned.m8n8.x4.shared.b16 {%0,%1,%2,%3}, [%4];" \
                 : "=r"(r0), "=r"(r1), "=r"(r2), "=r"(r3) : "r"(addr))

#define MMA16816H(c, a, b) \
    asm volatile("mma.sync.aligned.m16n8k16.row.col.f32.f16.f16.f32 " \
                 "{%0,%1,%2,%3}, {%4,%5,%6,%7}, {%8,%9}, {%0,%1,%2,%3};" \
                 : "+f"((c)[0]), "+f"((c)[1]), "+f"((c)[2]), "+f"((c)[3]) \
                 : "r"((a)[0]), "r"((a)[1]), "r"((a)[2]), "r"((a)[3]), \
                   "r"((b)[0]), "r"((b)[1]))

#define CP16(dst, gsrc) \
    asm volatile("cp.async.ca.shared.global [%0], [%1], 16;" \
                 :: "r"(dst), "l"(gsrc) : "memory")
#define CP_COMMIT() asm volatile("cp.async.commit_group;" ::: "memory")
#define CP_WAIT0()  asm volatile("cp.async.wait_group 0;" ::: "memory")

// ============================================================================
// Kernel 0: convert Wk/Wv to fp16.  grid=512, block=256
// ============================================================================
__global__ void wsplit_kernel(const float* __restrict__ Wk,
                              const float* __restrict__ Wv)
{
    const int sel = blockIdx.x & 1;
    const int i   = (blockIdx.x >> 1) * 256 + threadIdx.x;
    g_wh[sel][i] = __float2half_rn((sel ? Wv : Wk)[i]);
}

// ============================================================================
// Kernel 1: q = LN_perhead(x_q @ Wq^T) * scale          grid=B, block=256
// ============================================================================
__global__ void qproj_kernel(const float* __restrict__ xq,
                             const float* __restrict__ Wq,
                             const float* __restrict__ qn_w,
                             const float* __restrict__ qn_b)
{
    const int b = blockIdx.x;
    const int j = threadIdx.x;
    const int lane = j & 31;

    __shared__ float xrow[D_SZ];
    xrow[j] = xq[b * D_SZ + j];
    __syncthreads();

    const float4* w4 = reinterpret_cast<const float4*>(Wq + (size_t)j * D_SZ);
    const float4* x4 = reinterpret_cast<const float4*>(xrow);
    float acc = 0.f;
#pragma unroll
    for (int d = 0; d < D_SZ / 4; ++d) {
        float4 w = w4[d];
        float4 x = x4[d];
        acc = fmaf(w.x, x.x, acc);
        acc = fmaf(w.y, x.y, acc);
        acc = fmaf(w.z, x.z, acc);
        acc = fmaf(w.w, x.w, acc);
    }
    float s = acc, ss = acc * acc;
#pragma unroll
    for (int o = 16; o > 0; o >>= 1) {
        s  += __shfl_xor_sync(0xffffffffu, s,  o);
        ss += __shfl_xor_sync(0xffffffffu, ss, o);
    }
    const float mu  = s * (1.f / 32.f);
    const float var = ss * (1.f / 32.f) - mu * mu;
    const float r   = rsqrtf(var + EPS_LN);
    float q = (acc - mu) * r * qn_w[lane] + qn_b[lane];
    g_q[b * D_SZ + j] = q * Q_SCALE;
}

// ============================================================================
// Kernel 2 (mma.sync fp16, 2-pass X-split): Out[M,256] = X[M,256] @ W^T
//   CTA: M=64, N=256, K chunks of 64, double-buffered smem, SW128 swizzle.
//   512 threads / 16 warps; warp (mh, h) owns rows [32mh,+32) x cols [32h,+32).
//   2 MMA passes: Xhi*W16 + Xlo*W16  (drops only W's fp16 rounding, ~2e-4).
// ============================================================================
#define CH       64
#define NCH      (D_SZ / CH)      // 4
#define OFF_AH   0                 // 64 rows * 128B = 8 KB
#define OFF_AL   8192
#define OFF_WH   16384             // 256 rows * 128B = 32 KB
#define STAGE_B  49152             // 48 KB per stage
#define DSM_B    (2 * STAGE_B + 1024)
#define PT       512

template<bool DO_LN>
__global__ void __launch_bounds__(PT, 1)
proj_mma(const float* __restrict__ X, int wsel,
         const float* __restrict__ lnw, const float* __restrict__ lnb)
{
    extern __shared__ char dsm[];
    char* smp = (char*)((((uintptr_t)dsm) + 1023) & ~(uintptr_t)1023);
    const uint32_t base = smem_u32(smp);

    const int tid  = threadIdx.x;
    const int wid  = tid >> 5;
    const int lane = tid & 31;
    const int mh   = wid >> 3;       // 0/1 : 32-row half
    const int h    = wid & 7;        // head / 32-col stripe
    const size_t m_base = (size_t)blockIdx.x * 64;

    const __half* __restrict__ Wh = g_wh[wsel];

    float lw[4][2], lb[4][2];
    if (DO_LN) {
#pragma unroll
        for (int j = 0; j < 4; ++j) {
            const int c = 8 * j + 2 * (lane & 3);
            lw[j][0] = lnw[c];     lw[j][1] = lnw[c + 1];
            lb[j][0] = lnb[c];     lb[j][1] = lnb[c + 1];
        }
    }

    // ---- X load/convert mapping: thread -> row tid>>3, 8 floats ----
    const int xrow = tid >> 3;             // 0..63
    const int xc8  = tid & 7;              // 8-float group in 64-chunk
    const float* xptr = X + (m_base + xrow) * D_SZ + xc8 * 8;
    const uint32_t xoff = (uint32_t)xrow * 128u +
                          (((uint32_t)xc8 * 16u) ^ ((uint32_t)(xrow & 7) * 16u));

    float acc[2][4][4];
#pragma unroll
    for (int i = 0; i < 2; ++i)
#pragma unroll
        for (int j = 0; j < 4; ++j)
#pragma unroll
            for (int cc = 0; cc < 4; ++cc) acc[i][j][cc] = 0.f;

    float4 xr[2];

    // stage X (hi/lo fp16) into buffer `ab`
    auto stage_x = [&](char* ab) {
        float hx[8], lx[8];
        const float* xf = reinterpret_cast<const float*>(xr);
#pragma unroll
        for (int e = 0; e < 8; ++e) {
            hx[e] = __half2float(__float2half_rn(xf[e]));
            lx[e] = xf[e] - hx[e];
        }
        uint4 hv, lv;
        hv.x = pack_h2(hx[0], hx[1]); hv.y = pack_h2(hx[2], hx[3]);
        hv.z = pack_h2(hx[4], hx[5]); hv.w = pack_h2(hx[6], hx[7]);
        lv.x = pack_h2(lx[0], lx[1]); lv.y = pack_h2(lx[2], lx[3]);
        lv.z = pack_h2(lx[4], lx[5]); lv.w = pack_h2(lx[6], lx[7]);
        *reinterpret_cast<uint4*>(ab + OFF_AH + xoff) = hv;
        *reinterpret_cast<uint4*>(ab + OFF_AL + xoff) = lv;
    };

    // ================= prologue: stage 0 = chunk 0 =================
    {
        const uint32_t wb = base;
#pragma unroll
        for (int i = 0; i < 4; ++i) {
            const int idx = tid + i * PT;
            const int row = idx >> 3;
            const int j16 = idx & 7;
            const uint32_t off = (uint32_t)row * 128u +
                                 (((uint32_t)j16 * 16u) ^ ((uint32_t)(row & 7) * 16u));
            CP16(wb + OFF_WH + off, (const char*)Wh + (size_t)row * 512 + j16 * 16);
        }
        CP_COMMIT();
        xr[0] = *reinterpret_cast<const float4*>(xptr);
        xr[1] = *reinterpret_cast<const float4*>(xptr + 4);
        stage_x(smp);
        CP_WAIT0();
        __syncthreads();
    }

    // ================= main loop over K chunks =================
    for (int c = 0; c < NCH; ++c) {
        const int s = c & 1;
        const uint32_t sb = base + s * STAGE_B;

        if (c + 1 < NCH) {
            const int kn = (c + 1) * CH;
            const uint32_t wb = base + (s ^ 1) * STAGE_B;
#pragma unroll
            for (int i = 0; i < 4; ++i) {
                const int idx = tid + i * PT;
                const int row = idx >> 3;
                const int j16 = idx & 7;
                const uint32_t off = (uint32_t)row * 128u +
                                     (((uint32_t)j16 * 16u) ^ ((uint32_t)(row & 7) * 16u));
                CP16(wb + OFF_WH + off,
                     (const char*)Wh + (size_t)row * 512 + kn * 2 + j16 * 16);
            }
            CP_COMMIT();
            xr[0] = *reinterpret_cast<const float4*>(xptr + kn);
            xr[1] = *reinterpret_cast<const float4*>(xptr + kn + 4);
        }

        // ---------------- compute chunk c ----------------
#pragma unroll
        for (int ks = 0; ks < 4; ++ks) {
            uint32_t Ah4[2][4], Al4[2][4], Bh4[4][2];
            {
                const int ar = lane & 15;
                const uint32_t akhb = (uint32_t)(lane >> 4) * 16u;
#pragma unroll
                for (int i = 0; i < 2; ++i) {
                    const int row = 32 * mh + 16 * i + ar;
                    const uint32_t off = (uint32_t)row * 128u +
                        (((uint32_t)ks * 32u + akhb) ^ ((uint32_t)(row & 7) * 16u));
                    LDSM4(Ah4[i][0], Ah4[i][1], Ah4[i][2], Ah4[i][3], sb + OFF_AH + off);
                    LDSM4(Al4[i][0], Al4[i][1], Al4[i][2], Al4[i][3], sb + OFF_AL + off);
                }
            }
            {
                const int g2  = lane >> 3;
                const uint32_t khb = (uint32_t)(g2 & 1) * 16u;
                const int rsub = ((g2 >> 1) * 8) + (lane & 7);
#pragma unroll
                for (int p = 0; p < 2; ++p) {
                    const int row = h * 32 + p * 16 + rsub;
                    const uint32_t off = (uint32_t)row * 128u +
                        (((uint32_t)ks * 32u + khb) ^ ((uint32_t)(row & 7) * 16u));
                    LDSM4(Bh4[2 * p][0], Bh4[2 * p][1], Bh4[2 * p + 1][0], Bh4[2 * p + 1][1],
                          sb + OFF_WH + off);
                }
            }
#pragma unroll
            for (int i = 0; i < 2; ++i)
#pragma unroll
                for (int j = 0; j < 4; ++j) {
                    MMA16816H(acc[i][j], Ah4[i], Bh4[j]);
                    MMA16816H(acc[i][j], Al4[i], Bh4[j]);
                }
        }

        // ---------------- stage X for chunk c+1 ----------------
        if (c + 1 < NCH) {
            stage_x(smp + (s ^ 1) * STAGE_B);
            CP_WAIT0();
        }
        __syncthreads();
    }

    // ================= epilogue: per-head LN + store =================
    float* __restrict__ Out = DO_LN ? g_k : g_v;
    const int g  = lane >> 2;
    const int tg = lane & 3;
    const int ncol = h * 32 + 2 * tg;

#pragma unroll
    for (int i = 0; i < 2; ++i) {
#pragma unroll
        for (int half = 0; half < 2; ++half) {
            const int r = 32 * mh + 16 * i + 8 * half + g;
            float v0[4], v1[4];
#pragma unroll
            for (int j = 0; j < 4; ++j) {
                v0[j] = acc[i][j][2 * half];
                v1[j] = acc[i][j][2 * half + 1];
            }
            if (DO_LN) {
                float s = 0.f, ss = 0.f;
#pragma unroll
                for (int j = 0; j < 4; ++j) {
                    s  += v0[j] + v1[j];
                    ss += v0[j] * v0[j] + v1[j] * v1[j];
                }
                s  += __shfl_xor_sync(0xffffffffu, s,  1);
                ss += __shfl_xor_sync(0xffffffffu, ss, 1);
                s  += __shfl_xor_sync(0xffffffffu, s,  2);
                ss += __shfl_xor_sync(0xffffffffu, ss, 2);
                const float mu  = s * (1.f / 32.f);
                const float var = ss * (1.f / 32.f) - mu * mu;
                const float rr  = rsqrtf(var + EPS_LN);
#pragma unroll
                for (int j = 0; j < 4; ++j) {
                    v0[j] = (v0[j] - mu) * rr * lw[j][0] + lb[j][0];
                    v1[j] = (v1[j] - mu) * rr * lw[j][1] + lb[j][1];
                }
            }
            float* orow = Out + (m_base + r) * D_SZ + ncol;
#pragma unroll
            for (int j = 0; j < 4; ++j)
                *reinterpret_cast<float2*>(orow + 8 * j) = make_float2(v0[j], v1[j]);
        }
    }
}

// ============================================================================
// Kernel 3: attention. grid=B, block=512. 2 warps per head (split K range),
//   lane = channel (coalesced 128B/row/warp), prefetch-pipelined loads.
//   Merge flash states in smem, then block LN + Wp GEMV (split-K over 2 thr).
// ============================================================================
#define ATTN_SETS 32   // per warp: 256 rows / 8

__global__ void __launch_bounds__(512, 2)
attn_kernel(const float* __restrict__ Wp,
            const float* __restrict__ n_w,
            const float* __restrict__ n_b,
            float* __restrict__ out)
{
    const int b    = blockIdx.x;
    const int tid  = threadIdx.x;
    const int w    = tid >> 5;
    const int lane = tid & 31;
    const int h    = w & 7;
    const int khalf = w >> 3;      // 0/1 : K rows [0,256) or [256,512)

    const float q = g_q[b * D_SZ + h * HD_SZ + lane];
    const float* kp = g_k + (size_t)b * K_SZ * D_SZ + (size_t)khalf * 256 * D_SZ
                          + h * HD_SZ + lane;
    const float* vp = g_v + (size_t)b * K_SZ * D_SZ + (size_t)khalf * 256 * D_SZ
                          + h * HD_SZ + lane;

    float m = -1e30f, l = 0.f, o = 0.f;

    float ka[8], va[8], kb[8], vb[8];

#define LOADSET(s, K, V) do {                                         \
    _Pragma("unroll")                                                 \
    for (int u = 0; u < 8; ++u) {                                     \
        K[u] = kp[((s) * 8 + u) * D_SZ];                              \
        V[u] = vp[((s) * 8 + u) * D_SZ];                              \
    } } while (0)

#define PROCESS(K, V) do {                                            \
    float s8[8];                                                      \
    _Pragma("unroll")                                                 \
    for (int u = 0; u < 8; ++u) s8[u] = q * K[u];                     \
    _Pragma("unroll")                                                 \
    for (int off = 16; off > 0; off >>= 1) {                          \
        _Pragma("unroll")                                             \
        for (int u = 0; u < 8; ++u)                                   \
            s8[u] += __shfl_xor_sync(0xffffffffu, s8[u], off);        \
    }                                                                 \
    float mb = s8[0];                                                 \
    _Pragma("unroll")                                                 \
    for (int u = 1; u < 8; ++u) mb = fmaxf(mb, s8[u]);                \
    const float mn   = fmaxf(m, mb);                                  \
    const float corr = __expf(m - mn);                                \
    l *= corr;  o *= corr;                                            \
    _Pragma("unroll")                                                 \
    for (int u = 0; u < 8; ++u) {                                     \
        const float p = __expf(s8[u] - mn);                           \
        l += p;                                                       \
        o = fmaf(p, V[u], o);                                         \
    }                                                                 \
    m = mn; } while (0)

    LOADSET(0, ka, va);
#pragma unroll 1
    for (int it = 0; it < ATTN_SETS; it += 2) {
        LOADSET(it + 1, kb, vb);
        PROCESS(ka, va);
        if (it + 2 < ATTN_SETS) LOADSET(it + 2, ka, va);
        PROCESS(kb, vb);
    }
#undef LOADSET
#undef PROCESS

    // ---- merge the two K-half states per head ----
    __shared__ float sm16[16], sl16[16], so16[16][33];
    sm16[w] = m;  sl16[w] = l;  so16[w][lane] = o;
    __syncthreads();

    float o_val = 0.f;
    if (w < 8) {
        const float m0 = sm16[w], m1 = sm16[w + 8];
        const float M  = fmaxf(m0, m1);
        const float c0 = __expf(m0 - M), c1 = __expf(m1 - M);
        const float L  = sl16[w] * c0 + sl16[w + 8] * c1;
        o_val = (so16[w][lane] * c0 + so16[w + 8][lane] * c1) / L;
    }

    // ---- block LN over 256 channels (threads 0..255 hold o_val) ----
    __shared__ float sred[2][8];
    if (w < 8) {
        float s = o_val, ss = o_val * o_val;
#pragma unroll
        for (int off = 16; off > 0; off >>= 1) {
            s  += __shfl_xor_sync(0xffffffffu, s,  off);
            ss += __shfl_xor_sync(0xffffffffu, ss, off);
        }
        if (lane == 0) { sred[0][h] = s; sred[1][h] = ss; }
    }
    __syncthreads();
    float ts = 0.f, tss = 0.f;
#pragma unroll
    for (int i = 0; i < 8; ++i) { ts += sred[0][i]; tss += sred[1][i]; }
    const float mu  = ts * (1.f / 256.f);
    const float var = tss * (1.f / 256.f) - mu * mu;
    const float rln = rsqrtf(var + EPS_LN);

    __shared__ float sn[D_SZ];
    if (w < 8)
        sn[tid] = (o_val - mu) * rln * n_w[tid] + n_b[tid];
    __syncthreads();

    // ---- out @ Wp^T : 2 threads per output column (split K 128+128) ----
    const int c   = tid & 255;
    const int seg = tid >> 8;
    const float4* w4 = reinterpret_cast<const float4*>(Wp + (size_t)c * D_SZ + seg * 128);
    const float4* x4 = reinterpret_cast<const float4*>(sn + seg * 128);
    float a = 0.f;
#pragma unroll
    for (int d = 0; d < 32; ++d) {
        float4 wv = w4[d];
        float4 xv = x4[d];
        a = fmaf(wv.x, xv.x, a);
        a = fmaf(wv.y, xv.y, a);
        a = fmaf(wv.z, xv.z, a);
        a = fmaf(wv.w, xv.w, a);
    }
    __shared__ float part[256];
    if (seg == 1) part[c] = a;
    __syncthreads();
    if (seg == 0) out[b * D_SZ + c] = a + part[c];
}

// ============================================================================
extern "C" void kernel_launch(void* const* d_in, const int* in_sizes, int n_in,
                              void* d_out, int out_size)
{
    const float* x_q  = (const float*)d_in[0];
    const float* x_k  = (const float*)d_in[1];
    const float* x_v  = (const float*)d_in[2];
    const float* Wq   = (const float*)d_in[3];
    const float* Wk   = (const float*)d_in[4];
    const float* Wv   = (const float*)d_in[5];
    const float* Wp   = (const float*)d_in[6];
    const float* qn_w = (const float*)d_in[7];
    const float* qn_b = (const float*)d_in[8];
    const float* kn_w = (const float*)d_in[9];
    const float* kn_b = (const float*)d_in[10];
    const float* n_w  = (const float*)d_in[11];
    const float* n_b  = (const float*)d_in[12];
    float* out = (float*)d_out;

    static int smem_set = 0;
    if (!smem_set) {
        cudaFuncSetAttribute(proj_mma<true>,
                             cudaFuncAttributeMaxDynamicSharedMemorySize, DSM_B);
        cudaFuncSetAttribute(proj_mma<false>,
                             cudaFuncAttributeMaxDynamicSharedMemorySize, DSM_B);
        smem_set = 1;
    }

    const int M_TILES = (B_SZ * K_SZ) / 64;   // 8192

    wsplit_kernel<<<512, 256>>>(Wk, Wv);
    qproj_kernel<<<B_SZ, 256>>>(x_q, Wq, qn_w, qn_b);
    proj_mma<true ><<<M_TILES, PT, DSM_B>>>(x_k, 0, kn_w, kn_b);
    proj_mma<false><<<M_TILES, PT, DSM_B>>>(x_v, 1, nullptr, nullptr);
    attn_kernel<<<B_SZ, 512>>>(Wp, n_w, n_b, out);
}

// round 10
// speedup vs baseline: 1.7440x; 1.2438x over previous
#include <cuda_runtime.h>
#include <cuda_bf16.h>
#include <cuda_fp16.h>
#include <cstdint>

#define B_SZ   1024
#define K_SZ   512
#define D_SZ   256
#define H_SZ   8
#define HD_SZ  32
#define EPS_LN 1e-5f
#define Q_SCALE 0.17677669529663687f   // 32^-0.5

// ---------------- scratch (device globals; allocation-free) ----------------
__device__ float  g_q[B_SZ * D_SZ];                       // 1 MB
__device__ __half g_kh[(size_t)B_SZ * K_SZ * D_SZ];       // 256 MB (LN'd k, fp16)
__device__ __half g_vh[(size_t)B_SZ * K_SZ * D_SZ];       // 256 MB (v, fp16)
__device__ __half g_wh[2][D_SZ * D_SZ];                   // W fp16 (0=Wk,1=Wv)

// ======================= helpers ==============================
__device__ __forceinline__ uint32_t smem_u32(const void* p) {
    uint32_t a;
    asm("{ .reg .u64 t; cvta.to.shared.u64 t, %1; cvt.u32.u64 %0, t; }"
        : "=r"(a) : "l"(p));
    return a;
}
__device__ __forceinline__ uint32_t pack_h2(float a, float b) {
    __half2 t = __floats2half2_rn(a, b);
    return *reinterpret_cast<uint32_t*>(&t);
}

#define LDSM4(r0, r1, r2, r3, addr) \
    asm volatile("ldmatrix.sync.aligned.m8n8.x4.shared.b16 {%0,%1,%2,%3}, [%4];" \
                 : "=r"(r0), "=r"(r1), "=r"(r2), "=r"(r3) : "r"(addr))

#define MMA16816H(c, a, b) \
    asm volatile("mma.sync.aligned.m16n8k16.row.col.f32.f16.f16.f32 " \
                 "{%0,%1,%2,%3}, {%4,%5,%6,%7}, {%8,%9}, {%0,%1,%2,%3};" \
                 : "+f"((c)[0]), "+f"((c)[1]), "+f"((c)[2]), "+f"((c)[3]) \
                 : "r"((a)[0]), "r"((a)[1]), "r"((a)[2]), "r"((a)[3]), \
                   "r"((b)[0]), "r"((b)[1]))

#define CP16(dst, gsrc) \
    asm volatile("cp.async.ca.shared.global [%0], [%1], 16;" \
                 :: "r"(dst), "l"(gsrc) : "memory")
#define CP_COMMIT() asm volatile("cp.async.commit_group;" ::: "memory")
#define CP_WAIT0()  asm volatile("cp.async.wait_group 0;" ::: "memory")

// ============================================================================
// Kernel 0: convert Wk/Wv to fp16.  grid=512, block=256
// ============================================================================
__global__ void wsplit_kernel(const float* __restrict__ Wk,
                              const float* __restrict__ Wv)
{
    const int sel = blockIdx.x & 1;
    const int i   = (blockIdx.x >> 1) * 256 + threadIdx.x;
    g_wh[sel][i] = __float2half_rn((sel ? Wv : Wk)[i]);
}

// ============================================================================
// Kernel 1: q = LN_perhead(x_q @ Wq^T) * scale          grid=B, block=256
// ============================================================================
__global__ void qproj_kernel(const float* __restrict__ xq,
                             const float* __restrict__ Wq,
                             const float* __restrict__ qn_w,
                             const float* __restrict__ qn_b)
{
    const int b = blockIdx.x;
    const int j = threadIdx.x;
    const int lane = j & 31;

    __shared__ float xrow[D_SZ];
    xrow[j] = xq[b * D_SZ + j];
    __syncthreads();

    const float4* w4 = reinterpret_cast<const float4*>(Wq + (size_t)j * D_SZ);
    const float4* x4 = reinterpret_cast<const float4*>(xrow);
    float acc = 0.f;
#pragma unroll
    for (int d = 0; d < D_SZ / 4; ++d) {
        float4 w = w4[d];
        float4 x = x4[d];
        acc = fmaf(w.x, x.x, acc);
        acc = fmaf(w.y, x.y, acc);
        acc = fmaf(w.z, x.z, acc);
        acc = fmaf(w.w, x.w, acc);
    }
    float s = acc, ss = acc * acc;
#pragma unroll
    for (int o = 16; o > 0; o >>= 1) {
        s  += __shfl_xor_sync(0xffffffffu, s,  o);
        ss += __shfl_xor_sync(0xffffffffu, ss, o);
    }
    const float mu  = s * (1.f / 32.f);
    const float var = ss * (1.f / 32.f) - mu * mu;
    const float r   = rsqrtf(var + EPS_LN);
    float q = (acc - mu) * r * qn_w[lane] + qn_b[lane];
    g_q[b * D_SZ + j] = q * Q_SCALE;
}

// ============================================================================
// Kernel 2 (mma.sync fp16, 1-pass): Out[M,256] = fp16(X)[M,256] @ fp16(W)^T
//   CTA: M=64, N=256, K chunks of 64, double-buffered smem, SW128 swizzle.
//   512 threads / 16 warps; warp (mh, h) owns rows [32mh,+32) x cols [32h,+32).
//   Epilogue: per-head LN (K path), store fp16 k/v.
// ============================================================================
#define CH       64
#define NCH      (D_SZ / CH)      // 4
#define OFF_A    0                 // 64 rows * 128B = 8 KB
#define OFF_W    8192              // 256 rows * 128B = 32 KB
#define STAGE_B  40960             // 40 KB per stage
#define DSM_B    (2 * STAGE_B + 1024)
#define PT       512

template<bool DO_LN>
__global__ void __launch_bounds__(PT, 1)
proj_mma(const float* __restrict__ X, int wsel,
         const float* __restrict__ lnw, const float* __restrict__ lnb)
{
    extern __shared__ char dsm[];
    char* smp = (char*)((((uintptr_t)dsm) + 1023) & ~(uintptr_t)1023);
    const uint32_t base = smem_u32(smp);

    const int tid  = threadIdx.x;
    const int wid  = tid >> 5;
    const int lane = tid & 31;
    const int mh   = wid >> 3;       // 0/1 : 32-row half
    const int h    = wid & 7;        // head / 32-col stripe
    const size_t m_base = (size_t)blockIdx.x * 64;

    const __half* __restrict__ Wh = g_wh[wsel];

    float lw[4][2], lb[4][2];
    if (DO_LN) {
#pragma unroll
        for (int j = 0; j < 4; ++j) {
            const int c = 8 * j + 2 * (lane & 3);
            lw[j][0] = lnw[c];     lw[j][1] = lnw[c + 1];
            lb[j][0] = lnb[c];     lb[j][1] = lnb[c + 1];
        }
    }

    // ---- X load/convert mapping: thread -> row tid>>3, 8 floats ----
    const int xrow = tid >> 3;             // 0..63
    const int xc8  = tid & 7;              // 8-float group in 64-chunk
    const float* xptr = X + (m_base + xrow) * D_SZ + xc8 * 8;
    const uint32_t xoff = (uint32_t)xrow * 128u +
                          (((uint32_t)xc8 * 16u) ^ ((uint32_t)(xrow & 7) * 16u));

    float acc[2][4][4];
#pragma unroll
    for (int i = 0; i < 2; ++i)
#pragma unroll
        for (int j = 0; j < 4; ++j)
#pragma unroll
            for (int cc = 0; cc < 4; ++cc) acc[i][j][cc] = 0.f;

    float4 xr[2];

    auto stage_x = [&](char* ab) {
        const float* xf = reinterpret_cast<const float*>(xr);
        uint4 hv;
        hv.x = pack_h2(xf[0], xf[1]); hv.y = pack_h2(xf[2], xf[3]);
        hv.z = pack_h2(xf[4], xf[5]); hv.w = pack_h2(xf[6], xf[7]);
        *reinterpret_cast<uint4*>(ab + OFF_A + xoff) = hv;
    };

    // ================= prologue: stage 0 = chunk 0 =================
    {
        const uint32_t wb = base;
#pragma unroll
        for (int i = 0; i < 4; ++i) {
            const int idx = tid + i * PT;
            const int row = idx >> 3;
            const int j16 = idx & 7;
            const uint32_t off = (uint32_t)row * 128u +
                                 (((uint32_t)j16 * 16u) ^ ((uint32_t)(row & 7) * 16u));
            CP16(wb + OFF_W + off, (const char*)Wh + (size_t)row * 512 + j16 * 16);
        }
        CP_COMMIT();
        xr[0] = *reinterpret_cast<const float4*>(xptr);
        xr[1] = *reinterpret_cast<const float4*>(xptr + 4);
        stage_x(smp);
        CP_WAIT0();
        __syncthreads();
    }

    // ================= main loop over K chunks =================
    for (int c = 0; c < NCH; ++c) {
        const int s = c & 1;
        const uint32_t sb = base + s * STAGE_B;

        if (c + 1 < NCH) {
            const int kn = (c + 1) * CH;
            const uint32_t wb = base + (s ^ 1) * STAGE_B;
#pragma unroll
            for (int i = 0; i < 4; ++i) {
                const int idx = tid + i * PT;
                const int row = idx >> 3;
                const int j16 = idx & 7;
                const uint32_t off = (uint32_t)row * 128u +
                                     (((uint32_t)j16 * 16u) ^ ((uint32_t)(row & 7) * 16u));
                CP16(wb + OFF_W + off,
                     (const char*)Wh + (size_t)row * 512 + kn * 2 + j16 * 16);
            }
            CP_COMMIT();
            xr[0] = *reinterpret_cast<const float4*>(xptr + kn);
            xr[1] = *reinterpret_cast<const float4*>(xptr + kn + 4);
        }

        // ---------------- compute chunk c ----------------
#pragma unroll
        for (int ks = 0; ks < 4; ++ks) {
            uint32_t Ah4[2][4], Bh4[4][2];
            {
                const int ar = lane & 15;
                const uint32_t akhb = (uint32_t)(lane >> 4) * 16u;
#pragma unroll
                for (int i = 0; i < 2; ++i) {
                    const int row = 32 * mh + 16 * i + ar;
                    const uint32_t off = (uint32_t)row * 128u +
                        (((uint32_t)ks * 32u + akhb) ^ ((uint32_t)(row & 7) * 16u));
                    LDSM4(Ah4[i][0], Ah4[i][1], Ah4[i][2], Ah4[i][3], sb + OFF_A + off);
                }
            }
            {
                const int g2  = lane >> 3;
                const uint32_t khb = (uint32_t)(g2 & 1) * 16u;
                const int rsub = ((g2 >> 1) * 8) + (lane & 7);
#pragma unroll
                for (int p = 0; p < 2; ++p) {
                    const int row = h * 32 + p * 16 + rsub;
                    const uint32_t off = (uint32_t)row * 128u +
                        (((uint32_t)ks * 32u + khb) ^ ((uint32_t)(row & 7) * 16u));
                    LDSM4(Bh4[2 * p][0], Bh4[2 * p][1], Bh4[2 * p + 1][0], Bh4[2 * p + 1][1],
                          sb + OFF_W + off);
                }
            }
#pragma unroll
            for (int i = 0; i < 2; ++i)
#pragma unroll
                for (int j = 0; j < 4; ++j)
                    MMA16816H(acc[i][j], Ah4[i], Bh4[j]);
        }

        // ---------------- stage X for chunk c+1 ----------------
        if (c + 1 < NCH) {
            stage_x(smp + (s ^ 1) * STAGE_B);
            CP_WAIT0();
        }
        __syncthreads();
    }

    // ================= epilogue: per-head LN + fp16 store =================
    __half* __restrict__ Out = DO_LN ? g_kh : g_vh;
    const int g  = lane >> 2;
    const int tg = lane & 3;
    const int ncol = h * 32 + 2 * tg;

#pragma unroll
    for (int i = 0; i < 2; ++i) {
#pragma unroll
        for (int half = 0; half < 2; ++half) {
            const int r = 32 * mh + 16 * i + 8 * half + g;
            float v0[4], v1[4];
#pragma unroll
            for (int j = 0; j < 4; ++j) {
                v0[j] = acc[i][j][2 * half];
                v1[j] = acc[i][j][2 * half + 1];
            }
            if (DO_LN) {
                float s = 0.f, ss = 0.f;
#pragma unroll
                for (int j = 0; j < 4; ++j) {
                    s  += v0[j] + v1[j];
                    ss += v0[j] * v0[j] + v1[j] * v1[j];
                }
                s  += __shfl_xor_sync(0xffffffffu, s,  1);
                ss += __shfl_xor_sync(0xffffffffu, ss, 1);
                s  += __shfl_xor_sync(0xffffffffu, s,  2);
                ss += __shfl_xor_sync(0xffffffffu, ss, 2);
                const float mu  = s * (1.f / 32.f);
                const float var = ss * (1.f / 32.f) - mu * mu;
                const float rr  = rsqrtf(var + EPS_LN);
#pragma unroll
                for (int j = 0; j < 4; ++j) {
                    v0[j] = (v0[j] - mu) * rr * lw[j][0] + lb[j][0];
                    v1[j] = (v1[j] - mu) * rr * lw[j][1] + lb[j][1];
                }
            }
            __half* orow = Out + (m_base + r) * D_SZ + ncol;
#pragma unroll
            for (int j = 0; j < 4; ++j)
                *reinterpret_cast<__half2*>(orow + 8 * j) = __floats2half2_rn(v0[j], v1[j]);
        }
    }
}

// ============================================================================
// Kernel 3: attention over fp16 k/v. grid=B, block=512. 2 warps per head
//   (split K range), lane = channel, prefetch-pipelined loads.
// ============================================================================
#define ATTN_SETS 32   // per warp: 256 rows / 8

__global__ void __launch_bounds__(512, 2)
attn_kernel(const float* __restrict__ Wp,
            const float* __restrict__ n_w,
            const float* __restrict__ n_b,
            float* __restrict__ out)
{
    const int b    = blockIdx.x;
    const int tid  = threadIdx.x;
    const int w    = tid >> 5;
    const int lane = tid & 31;
    const int h    = w & 7;
    const int khalf = w >> 3;      // 0/1 : K rows [0,256) or [256,512)

    const float q = g_q[b * D_SZ + h * HD_SZ + lane];
    const __half* kp = g_kh + (size_t)b * K_SZ * D_SZ + (size_t)khalf * 256 * D_SZ
                           + h * HD_SZ + lane;
    const __half* vp = g_vh + (size_t)b * K_SZ * D_SZ + (size_t)khalf * 256 * D_SZ
                           + h * HD_SZ + lane;

    float m = -1e30f, l = 0.f, o = 0.f;

    float ka[8], va[8], kb[8], vb[8];

#define LOADSET(s, K, V) do {                                         \
    _Pragma("unroll")                                                 \
    for (int u = 0; u < 8; ++u) {                                     \
        K[u] = __half2float(kp[((s) * 8 + u) * D_SZ]);                \
        V[u] = __half2float(vp[((s) * 8 + u) * D_SZ]);                \
    } } while (0)

#define PROCESS(K, V) do {                                            \
    float s8[8];                                                      \
    _Pragma("unroll")                                                 \
    for (int u = 0; u < 8; ++u) s8[u] = q * K[u];                     \
    _Pragma("unroll")                                                 \
    for (int off = 16; off > 0; off >>= 1) {                          \
        _Pragma("unroll")                                             \
        for (int u = 0; u < 8; ++u)                                   \
            s8[u] += __shfl_xor_sync(0xffffffffu, s8[u], off);        \
    }                                                                 \
    float mb = s8[0];                                                 \
    _Pragma("unroll")                                                 \
    for (int u = 1; u < 8; ++u) mb = fmaxf(mb, s8[u]);                \
    const float mn   = fmaxf(m, mb);                                  \
    const float corr = __expf(m - mn);                                \
    l *= corr;  o *= corr;                                            \
    _Pragma("unroll")                                                 \
    for (int u = 0; u < 8; ++u) {                                     \
        const float p = __expf(s8[u] - mn);                           \
        l += p;                                                       \
        o = fmaf(p, V[u], o);                                         \
    }                                                                 \
    m = mn; } while (0)

    LOADSET(0, ka, va);
#pragma unroll 1
    for (int it = 0; it < ATTN_SETS; it += 2) {
        LOADSET(it + 1, kb, vb);
        PROCESS(ka, va);
        if (it + 2 < ATTN_SETS) LOADSET(it + 2, ka, va);
        PROCESS(kb, vb);
    }
#undef LOADSET
#undef PROCESS

    // ---- merge the two K-half states per head ----
    __shared__ float sm16[16], sl16[16], so16[16][33];
    sm16[w] = m;  sl16[w] = l;  so16[w][lane] = o;
    __syncthreads();

    float o_val = 0.f;
    if (w < 8) {
        const float m0 = sm16[w], m1 = sm16[w + 8];
        const float M  = fmaxf(m0, m1);
        const float c0 = __expf(m0 - M), c1 = __expf(m1 - M);
        const float L  = sl16[w] * c0 + sl16[w + 8] * c1;
        o_val = (so16[w][lane] * c0 + so16[w + 8][lane] * c1) / L;
    }

    // ---- block LN over 256 channels (threads 0..255 hold o_val) ----
    __shared__ float sred[2][8];
    if (w < 8) {
        float s = o_val, ss = o_val * o_val;
#pragma unroll
        for (int off = 16; off > 0; off >>= 1) {
            s  += __shfl_xor_sync(0xffffffffu, s,  off);
            ss += __shfl_xor_sync(0xffffffffu, ss, off);
        }
        if (lane == 0) { sred[0][h] = s; sred[1][h] = ss; }
    }
    __syncthreads();
    float ts = 0.f, tss = 0.f;
#pragma unroll
    for (int i = 0; i < 8; ++i) { ts += sred[0][i]; tss += sred[1][i]; }
    const float mu  = ts * (1.f / 256.f);
    const float var = tss * (1.f / 256.f) - mu * mu;
    const float rln = rsqrtf(var + EPS_LN);

    __shared__ float sn[D_SZ];
    if (w < 8)
        sn[tid] = (o_val - mu) * rln * n_w[tid] + n_b[tid];
    __syncthreads();

    // ---- out @ Wp^T : 2 threads per output column (split K 128+128) ----
    const int c   = tid & 255;
    const int seg = tid >> 8;
    const float4* w4 = reinterpret_cast<const float4*>(Wp + (size_t)c * D_SZ + seg * 128);
    const float4* x4 = reinterpret_cast<const float4*>(sn + seg * 128);
    float a = 0.f;
#pragma unroll
    for (int d = 0; d < 32; ++d) {
        float4 wv = w4[d];
        float4 xv = x4[d];
        a = fmaf(wv.x, xv.x, a);
        a = fmaf(wv.y, xv.y, a);
        a = fmaf(wv.z, xv.z, a);
        a = fmaf(wv.w, xv.w, a);
    }
    __shared__ float part[256];
    if (seg == 1) part[c] = a;
    __syncthreads();
    if (seg == 0) out[b * D_SZ + c] = a + part[c];
}

// ============================================================================
extern "C" void kernel_launch(void* const* d_in, const int* in_sizes, int n_in,
                              void* d_out, int out_size)
{
    const float* x_q  = (const float*)d_in[0];
    const float* x_k  = (const float*)d_in[1];
    const float* x_v  = (const float*)d_in[2];
    const float* Wq   = (const float*)d_in[3];
    const float* Wk   = (const float*)d_in[4];
    const float* Wv   = (const float*)d_in[5];
    const float* Wp   = (const float*)d_in[6];
    const float* qn_w = (const float*)d_in[7];
    const float* qn_b = (const float*)d_in[8];
    const float* kn_w = (const float*)d_in[9];
    const float* kn_b = (const float*)d_in[10];
    const float* n_w  = (const float*)d_in[11];
    const float* n_b  = (const float*)d_in[12];
    float* out = (float*)d_out;

    static int smem_set = 0;
    if (!smem_set) {
        cudaFuncSetAttribute(proj_mma<true>,
                             cudaFuncAttributeMaxDynamicSharedMemorySize, DSM_B);
        cudaFuncSetAttribute(proj_mma<false>,
                             cudaFuncAttributeMaxDynamicSharedMemorySize, DSM_B);
        smem_set = 1;
    }

    const int M_TILES = (B_SZ * K_SZ) / 64;   // 8192

    wsplit_kernel<<<512, 256>>>(Wk, Wv);
    qproj_kernel<<<B_SZ, 256>>>(x_q, Wq, qn_w, qn_b);
    proj_mma<true ><<<M_TILES, PT, DSM_B>>>(x_k, 0, kn_w, kn_b);
    proj_mma<false><<<M_TILES, PT, DSM_B>>>(x_v, 1, nullptr, nullptr);
    attn_kernel<<<B_SZ, 512>>>(Wp, n_w, n_b, out);
}